// round 11
// baseline (speedup 1.0000x reference)
#include <cuda_runtime.h>
#include <math.h>

#define N_NODES 8192
#define DIM     512
#define NBLK    128
#define NTHR    512

// ---------------------------------------------------------------------------
// Scratch (static device arrays — no allocations allowed)
// ---------------------------------------------------------------------------
__device__ float g_b[DIM];         // W @ a2
__device__ float g_s2[N_NODES];    // X @ b
__device__ float g_q[DIM];         // softmax(s2)^T @ X  (atomic accum)
__device__ float g_v[DIM];         // q @ W              (atomic accum)

// Sense-reversing grid barrier state. Counter self-resets every barrier, and
// 4 barriers/launch flip the sense an even number of times, so both words are
// replay-invariant (each CTA additionally samples the current sense at entry).
__device__ unsigned          g_bar_count = 0;
__device__ volatile unsigned g_bar_sense = 0;

// All 128 CTAs are co-resident by construction (128 blocks of 512 threads,
// ~2.6 KB smem => >=1 CTA/SM on 148 SMs; n_waves = 1), so spinning is
// deadlock-free.
__device__ __forceinline__ void grid_barrier(unsigned* sense_local) {
    __syncthreads();
    if (threadIdx.x == 0) {
        const unsigned expect = *sense_local ^ 1u;
        __threadfence();                                  // release phase data
        if (atomicAdd(&g_bar_count, 1u) == NBLK - 1u) {
            atomicExch(&g_bar_count, 0u);                 // reset for next use
            __threadfence();                              // reset before flip
            g_bar_sense = expect;                         // release all
        } else {
            while (g_bar_sense != expect) { __nanosleep(32); }
        }
        *sense_local = expect;
    }
    __threadfence();                                      // acquire (all threads)
    __syncthreads();
}

__device__ __forceinline__ float warp_sum(float v) {
#pragma unroll
    for (int o = 16; o; o >>= 1) v += __shfl_xor_sync(0xFFFFFFFFu, v, o);
    return v;
}

// ---------------------------------------------------------------------------
// Fused persistent kernel: out[i,:] = v = (softmax(X @ (W @ a2)))^T X W
// (softmax over s1[i]+s2[j] is row-invariant => all output rows identical)
// ---------------------------------------------------------------------------
__global__ __launch_bounds__(NTHR) void fca_fused(const float* __restrict__ X,
                                                  const float* __restrict__ W,
                                                  const float* __restrict__ av,
                                                  float* __restrict__ out) {
    __shared__ float4 s_vec[DIM / 4];   // b (phase 1) then v (phase 4)
    __shared__ float  red[32];
    __shared__ float  sp[64];
    __shared__ float  sMS[2];

    const int tid  = threadIdx.x;
    const int lane = tid & 31;
    const int warp = tid >> 5;

    unsigned sense = 0;
    if (tid == 0) sense = g_bar_sense;   // sampled before any flip is possible

    // ---- Phase 0: b[k] = W[k,:] . a2 (4 rows/block, warps 0..3), zero q/v --
    if (warp < 4) {
        const int k = blockIdx.x * 4 + warp;
        const float4* Wrow = reinterpret_cast<const float4*>(W + (size_t)k * DIM);
        const float4* a2v  = reinterpret_cast<const float4*>(av + DIM);
        float acc = 0.f;
#pragma unroll
        for (int it = 0; it < DIM / 128; ++it) {
            const int d4 = it * 32 + lane;
            float4 w = Wrow[d4];
            float4 a = a2v[d4];
            acc += w.x * a.x + w.y * a.y + w.z * a.z + w.w * a.w;
        }
        acc = warp_sum(acc);
        if (lane == 0) g_b[k] = acc;
    }
    if (tid < 4) {
        g_q[blockIdx.x * 4 + tid] = 0.f;
        g_v[blockIdx.x * 4 + tid] = 0.f;
    }

    grid_barrier(&sense);   // b complete, q/v zeroed

    // ---- Phase 1: s2[i] = X[i,:] . b   (64 rows/block, 4 rows/warp) --------
    if (tid < DIM / 4) s_vec[tid] = reinterpret_cast<const float4*>(g_b)[tid];
    __syncthreads();
    {
        const int row = blockIdx.x * 64 + warp * 4;
        const float4* Xr0 = reinterpret_cast<const float4*>(X + (size_t)(row + 0) * DIM);
        const float4* Xr1 = reinterpret_cast<const float4*>(X + (size_t)(row + 1) * DIM);
        const float4* Xr2 = reinterpret_cast<const float4*>(X + (size_t)(row + 2) * DIM);
        const float4* Xr3 = reinterpret_cast<const float4*>(X + (size_t)(row + 3) * DIM);
        float a0 = 0.f, a1 = 0.f, a2s = 0.f, a3 = 0.f;
#pragma unroll
        for (int it = 0; it < DIM / 128; ++it) {
            const int d4 = it * 32 + lane;
            float4 b  = s_vec[d4];
            float4 x0 = Xr0[d4];
            float4 x1 = Xr1[d4];
            float4 x2 = Xr2[d4];
            float4 x3 = Xr3[d4];
            a0  += x0.x * b.x + x0.y * b.y + x0.z * b.z + x0.w * b.w;
            a1  += x1.x * b.x + x1.y * b.y + x1.z * b.z + x1.w * b.w;
            a2s += x2.x * b.x + x2.y * b.y + x2.z * b.z + x2.w * b.w;
            a3  += x3.x * b.x + x3.y * b.y + x3.z * b.z + x3.w * b.w;
        }
        a0 = warp_sum(a0); a1 = warp_sum(a1); a2s = warp_sum(a2s); a3 = warp_sum(a3);
        if (lane == 0) {
            g_s2[row + 0] = a0;
            g_s2[row + 1] = a1;
            g_s2[row + 2] = a2s;
            g_s2[row + 3] = a3;
        }
    }

    grid_barrier(&sense);   // s2 complete

    // ---- Phase 2: per-block softmax normalization + q partial accumulation -
    {
        float vals[16];
        float m = -INFINITY;
#pragma unroll
        for (int i = 0; i < 16; ++i) {
            vals[i] = g_s2[tid + i * 512];
            m = fmaxf(m, vals[i]);
        }
#pragma unroll
        for (int o = 16; o; o >>= 1) m = fmaxf(m, __shfl_xor_sync(0xFFFFFFFFu, m, o));
        if (lane == 0) red[warp] = m;
        __syncthreads();
        if (warp == 0) {
            float M = (lane < 16) ? red[lane] : -INFINITY;
#pragma unroll
            for (int o = 16; o; o >>= 1) M = fmaxf(M, __shfl_xor_sync(0xFFFFFFFFu, M, o));
            if (lane == 0) sMS[0] = M;
        }
        __syncthreads();
        const float M = sMS[0];

        float s = 0.f;
#pragma unroll
        for (int i = 0; i < 16; ++i) s += __expf(vals[i] - M);
        s = warp_sum(s);
        if (lane == 0) red[warp] = s;
        __syncthreads();
        if (warp == 0) {
            float S = (lane < 16) ? red[lane] : 0.f;
#pragma unroll
            for (int o = 16; o; o >>= 1) S += __shfl_xor_sync(0xFFFFFFFFu, S, o);
            if (lane == 0) sMS[1] = 1.0f / S;
        }
        __syncthreads();
        const float invS = sMS[1];

        const int j0 = blockIdx.x * 64;
        if (tid < 64) sp[tid] = __expf(g_s2[j0 + tid] - M) * invS;
        __syncthreads();

        float acc = 0.f;
#pragma unroll 8
        for (int j = 0; j < 64; ++j)
            acc += sp[j] * X[(size_t)(j0 + j) * DIM + tid];
        atomicAdd(&g_q[tid], acc);
    }

    grid_barrier(&sense);   // q complete

    // ---- Phase 3: v[d] = sum_k q[k] * W[k][d]  (blocks 0..15 only) ---------
    if (blockIdx.x < 16) {
        if (tid < 32) sp[tid] = g_q[blockIdx.x * 32 + tid];
        __syncthreads();
        const int k0 = blockIdx.x * 32;
        float acc = 0.f;
#pragma unroll 8
        for (int k = 0; k < 32; ++k)
            acc += sp[k] * W[(size_t)(k0 + k) * DIM + tid];
        atomicAdd(&g_v[tid], acc);
    }

    grid_barrier(&sense);   // v complete

    // ---- Phase 4: out[i,:] = v  (16 MB streaming broadcast store) ----------
    if (tid < DIM / 4) s_vec[tid] = reinterpret_cast<const float4*>(g_v)[tid];
    __syncthreads();
    {
        float4* out4 = reinterpret_cast<float4*>(out);
        unsigned idx = blockIdx.x * NTHR + tid;
        const unsigned stride = NBLK * NTHR;             // 65536
#pragma unroll 16
        for (int it = 0; it < 16; ++it, idx += stride)   // 16*65536 = 1,048,576
            __stcs(&out4[idx], s_vec[idx & (DIM / 4 - 1)]);
    }
}

// ---------------------------------------------------------------------------
extern "C" void kernel_launch(void* const* d_in, const int* in_sizes, int n_in,
                              void* d_out, int out_size) {
    const float* X  = (const float*)d_in[0];  // node_features   [8192, 512]
    const float* W  = (const float*)d_in[1];  // weight_matrix   [512, 512]
    const float* av = (const float*)d_in[2];  // attention_vector[1024, 1]
    float* out = (float*)d_out;               // [8192, 512]

    (void)in_sizes; (void)n_in; (void)out_size;

    fca_fused<<<NBLK, NTHR>>>(X, W, av, out);
}

// round 15
// speedup vs baseline: 1.1916x; 1.1916x over previous
#include <cuda_runtime.h>
#include <math.h>

#define N_NODES 8192
#define DIM     512
#define NBLK    128
#define NTHR    512

// ---------------------------------------------------------------------------
// Scratch (static device arrays — no allocations allowed)
// ---------------------------------------------------------------------------
__device__ float g_b[DIM];          // W @ a2
__device__ float g_m[NBLK];         // per-block max of its 64 s2 values
__device__ float g_t[NBLK];         // per-block sum exp(s2 - m_b)
__device__ float g_q[DIM];          // softmax(s2)^T @ X  (atomic accum)
__device__ float g_v[DIM];          // q @ W              (atomic accum)

// Barrier state: count in one 128B line, sense in another (no polling vs
// arrival contention). Count self-resets; 4 barriers/launch = even sense
// flips, and each launch samples the live sense => replay-invariant.
__device__ unsigned g_sync[64];     // [0]=count, [32]=sense

// Release/acquire WITHOUT fence instructions: gpu-scope fences emit
// CCTL.IVALL (full L1D flush) which would kill X/W L1 reuse across phases.
// Instead: release-atomics for arrival/flip; consumers read cross-CTA data
// via __ldcg (L2-direct, immune to stale L1). X/W are immutable -> plain
// LDG, L1 stays warm across barriers.
__device__ __forceinline__ void grid_barrier(unsigned* sense_local) {
    __syncthreads();    // CTA-scope: all CTA threads' work done
    if (threadIdx.x == 0) {
        const unsigned expect = *sense_local ^ 1u;
        unsigned prev;
        asm volatile("atom.release.gpu.add.u32 %0, [%1], 1;"
                     : "=r"(prev) : "l"(&g_sync[0]) : "memory");
        if (prev == NBLK - 1u) {
            atomicExch(&g_sync[0], 0u);               // reset (L2-strong)
            asm volatile("st.release.gpu.u32 [%0], %1;"
                         :: "l"(&g_sync[32]), "r"(expect) : "memory");
        } else {
            unsigned cur;
            do {
                asm volatile("ld.relaxed.gpu.u32 %0, [%1];"
                             : "=r"(cur) : "l"(&g_sync[32]) : "memory");
            } while (cur != expect);
        }
        *sense_local = expect;
    }
    __syncthreads();
}

__device__ __forceinline__ float warp_max(float v) {
#pragma unroll
    for (int o = 16; o; o >>= 1) v = fmaxf(v, __shfl_xor_sync(0xFFFFFFFFu, v, o));
    return v;
}
__device__ __forceinline__ float warp_sum(float v) {
#pragma unroll
    for (int o = 16; o; o >>= 1) v += __shfl_xor_sync(0xFFFFFFFFu, v, o);
    return v;
}

// ---------------------------------------------------------------------------
// Fused persistent kernel: out[i,:] = v = (softmax(X @ (W @ a2)))^T X W
// (softmax over s1[i]+s2[j] is row-invariant => all output rows identical)
// Softmax normalizer via per-block log-sum-exp partials merged once
// (removes the 8192-exp-per-SM MUFU wall of the 25.3us version).
// ---------------------------------------------------------------------------
__global__ __launch_bounds__(NTHR) void fca_fused(const float* __restrict__ X,
                                                  const float* __restrict__ W,
                                                  const float* __restrict__ av,
                                                  float* __restrict__ out) {
    __shared__ float4 s_vec[DIM / 4];   // b (phase 1) then v (phase 4)
    __shared__ float  s_p[64];          // raw s2, then softmax weights
    __shared__ float  s_MS[2];          // M, 1/S

    const int tid  = threadIdx.x;
    const int lane = tid & 31;
    const int warp = tid >> 5;

    unsigned sense = 0;
    if (tid == 0) {
        asm volatile("ld.relaxed.gpu.u32 %0, [%1];"
                     : "=r"(sense) : "l"(&g_sync[32]) : "memory");
    }

    // ---- Phase 0: b[k] = W[k,:] . a2 (4 rows/block, warps 0..3); zero q/v --
    if (warp < 4) {
        const int k = blockIdx.x * 4 + warp;
        const float4* Wrow = reinterpret_cast<const float4*>(W + (size_t)k * DIM);
        const float4* a2v  = reinterpret_cast<const float4*>(av + DIM);
        float acc = 0.f;
#pragma unroll
        for (int it = 0; it < DIM / 128; ++it) {
            const int d4 = it * 32 + lane;
            float4 w = Wrow[d4];
            float4 a = a2v[d4];
            acc += w.x * a.x + w.y * a.y + w.z * a.z + w.w * a.w;
        }
        acc = warp_sum(acc);
        if (lane == 0) g_b[k] = acc;
    }
    if (tid < 4) {
        g_q[blockIdx.x * 4 + tid] = 0.f;
        g_v[blockIdx.x * 4 + tid] = 0.f;
    }

    grid_barrier(&sense);   // b complete, q/v zeroed

    // ---- Phase 1: s2 for own 64 rows -> smem; per-block (m_b, t_b) --------
    if (tid < DIM / 4)
        s_vec[tid] = __ldcg(reinterpret_cast<const float4*>(g_b) + tid);
    __syncthreads();
    {
        const int row = blockIdx.x * 64 + warp * 4;
        const float4* Xr0 = reinterpret_cast<const float4*>(X + (size_t)(row + 0) * DIM);
        const float4* Xr1 = reinterpret_cast<const float4*>(X + (size_t)(row + 1) * DIM);
        const float4* Xr2 = reinterpret_cast<const float4*>(X + (size_t)(row + 2) * DIM);
        const float4* Xr3 = reinterpret_cast<const float4*>(X + (size_t)(row + 3) * DIM);
        float a0 = 0.f, a1 = 0.f, a2s = 0.f, a3 = 0.f;
#pragma unroll
        for (int it = 0; it < DIM / 128; ++it) {
            const int d4 = it * 32 + lane;
            float4 b  = s_vec[d4];
            float4 x0 = Xr0[d4];
            float4 x1 = Xr1[d4];
            float4 x2 = Xr2[d4];
            float4 x3 = Xr3[d4];
            a0  += x0.x * b.x + x0.y * b.y + x0.z * b.z + x0.w * b.w;
            a1  += x1.x * b.x + x1.y * b.y + x1.z * b.z + x1.w * b.w;
            a2s += x2.x * b.x + x2.y * b.y + x2.z * b.z + x2.w * b.w;
            a3  += x3.x * b.x + x3.y * b.y + x3.z * b.z + x3.w * b.w;
        }
        a0 = warp_sum(a0); a1 = warp_sum(a1); a2s = warp_sum(a2s); a3 = warp_sum(a3);
        if (lane == 0) {
            s_p[warp * 4 + 0] = a0;
            s_p[warp * 4 + 1] = a1;
            s_p[warp * 4 + 2] = a2s;
            s_p[warp * 4 + 3] = a3;
        }
    }
    __syncthreads();
    if (warp == 0) {   // local log-sum-exp partial over this block's 64 rows
        const float v0 = s_p[lane], v1 = s_p[lane + 32];
        const float m  = warp_max(fmaxf(v0, v1));
        const float t  = warp_sum(__expf(v0 - m) + __expf(v1 - m));
        if (lane == 0) { g_m[blockIdx.x] = m; g_t[blockIdx.x] = t; }
    }

    grid_barrier(&sense);   // all (m_b, t_b) complete

    // ---- Phase 2: merge 128 partials -> (M, S); weights; q accumulation ---
    if (warp == 0) {
        float m0 = __ldcg(g_m + lane),      m1 = __ldcg(g_m + lane + 32);
        float m2 = __ldcg(g_m + lane + 64), m3 = __ldcg(g_m + lane + 96);
        const float M = warp_max(fmaxf(fmaxf(m0, m1), fmaxf(m2, m3)));
        float t0 = __ldcg(g_t + lane),      t1 = __ldcg(g_t + lane + 32);
        float t2 = __ldcg(g_t + lane + 64), t3 = __ldcg(g_t + lane + 96);
        const float S = warp_sum(t0 * __expf(m0 - M) + t1 * __expf(m1 - M) +
                                 t2 * __expf(m2 - M) + t3 * __expf(m3 - M));
        if (lane == 0) { s_MS[0] = M; s_MS[1] = 1.0f / S; }
    }
    __syncthreads();
    {
        const float M    = s_MS[0];
        const float invS = s_MS[1];
        if (tid < 64) s_p[tid] = __expf(s_p[tid] - M) * invS;
    }
    __syncthreads();
    {
        const int j0 = blockIdx.x * 64;
        float acc = 0.f;
#pragma unroll 16
        for (int j = 0; j < 64; ++j)           // same rows as phase 1: L1-hot
            acc += s_p[j] * X[(size_t)(j0 + j) * DIM + tid];
        atomicAdd(&g_q[tid], acc);
    }

    grid_barrier(&sense);   // q complete

    // ---- Phase 3: v partial — 4 W-rows per block (L1-hot from phase 0) ----
    {
        const int k0 = blockIdx.x * 4;
        const float q0 = __ldcg(g_q + k0 + 0);
        const float q1 = __ldcg(g_q + k0 + 1);
        const float q2 = __ldcg(g_q + k0 + 2);
        const float q3 = __ldcg(g_q + k0 + 3);
        float acc = q0 * W[(size_t)(k0 + 0) * DIM + tid]
                  + q1 * W[(size_t)(k0 + 1) * DIM + tid]
                  + q2 * W[(size_t)(k0 + 2) * DIM + tid]
                  + q3 * W[(size_t)(k0 + 3) * DIM + tid];
        atomicAdd(&g_v[tid], acc);
    }

    grid_barrier(&sense);   // v complete

    // ---- Phase 4: out[i,:] = v  (16 MB streaming broadcast store) ----------
    if (tid < DIM / 4)
        s_vec[tid] = __ldcg(reinterpret_cast<const float4*>(g_v) + tid);
    __syncthreads();
    {
        float4* out4 = reinterpret_cast<float4*>(out);
        unsigned idx = blockIdx.x * NTHR + tid;
        const unsigned stride = NBLK * NTHR;             // 65536
#pragma unroll 16
        for (int it = 0; it < 16; ++it, idx += stride)   // 16*65536 = 1,048,576
            __stcs(&out4[idx], s_vec[idx & (DIM / 4 - 1)]);
    }
}

// ---------------------------------------------------------------------------
extern "C" void kernel_launch(void* const* d_in, const int* in_sizes, int n_in,
                              void* d_out, int out_size) {
    const float* X  = (const float*)d_in[0];  // node_features   [8192, 512]
    const float* W  = (const float*)d_in[1];  // weight_matrix   [512, 512]
    const float* av = (const float*)d_in[2];  // attention_vector[1024, 1]
    float* out = (float*)d_out;               // [8192, 512]

    (void)in_sizes; (void)n_in; (void)out_size;

    fca_fused<<<NBLK, NTHR>>>(X, W, av, out);
}